// round 1
// baseline (speedup 1.0000x reference)
#include <cuda_runtime.h>
#include <math.h>

#define BATCH 2
#define NV    4096
#define NP1   1024
#define NP2   256

// ---------------------------------------------------------------------------
// Device scratch (allocation-free rule: __device__ globals)
// ---------------------------------------------------------------------------
__device__ float g_d0n  [3*896];
__device__ float g_dir1n[3*896];
__device__ float g_dir2n[3*1792];
__device__ float g_dir3n[3*1792];
__device__ float g_dir4n[3*3584];

__device__ int   g_idx10_0[BATCH*NV*10];
__device__ int   g_idx4_0 [BATCH*NV*4];
__device__ float g_dirs0  [BATCH*NV*10*3];
__device__ float g_fm0    [BATCH*NV*128];
__device__ float g_feat1  [BATCH*NV*1024];
__device__ float g_conv1  [BATCH*NV*128];
__device__ float g_fm1    [BATCH*NV*128];

__device__ float g_v1 [BATCH*NP1*3];
__device__ float g_f1 [BATCH*NP1*128];
__device__ int   g_idx10_1[BATCH*NP1*10];
__device__ int   g_idx4_1 [BATCH*NP1*4];
__device__ float g_dirs1  [BATCH*NP1*10*3];
__device__ float g_feat2  [BATCH*NP1*2048];
__device__ float g_conv2  [BATCH*NP1*256];
__device__ float g_fm2    [BATCH*NP1*256];
__device__ float g_feat3  [BATCH*NP1*2048];
__device__ float g_conv3  [BATCH*NP1*256];
__device__ float g_fm3    [BATCH*NP1*256];

__device__ float g_v2 [BATCH*NP2*3];
__device__ float g_f2 [BATCH*NP2*256];
__device__ int   g_idx10_2[BATCH*NP2*10];
__device__ float g_dirs2  [BATCH*NP2*10*3];
__device__ float g_feat4  [BATCH*NP2*4096];
__device__ float g_fm4    [BATCH*NP2*512];

__device__ int   g_n1[BATCH*NV];
__device__ int   g_n2[BATCH*NV];
__device__ float g_mean[512];
__device__ float g_rstd[512];

// ---------------------------------------------------------------------------
// Math helpers
// ---------------------------------------------------------------------------
// SiLU for arguments guaranteed in [-1,1] (dot of two unit vectors).
// sigmoid(y) ~= 0.5 + y*(1/4 - y^2/48 + y^4/480 - 17 y^6/80640 + 31 y^8/1451520)
// abs error <= ~2e-6 on [-1,1]. Runs on the FMA pipe (no MUFU).
__device__ __forceinline__ float silu_unit(float y) {
    float u = y * y;
    float p = fmaf(u, 2.1357672e-5f, -2.1081349e-4f);
    p = fmaf(u, p, 2.0833333e-3f);
    p = fmaf(u, p, -2.0833333e-2f);
    p = fmaf(u, p, 0.25f);
    float s = fmaf(y, p, 0.5f);
    return y * s;
}

// Full-range SiLU (used only ~3M times total; MUFU is fine here)
__device__ __forceinline__ float silu_full(float y) {
    return y / (1.0f + __expf(-y));
}

// ---------------------------------------------------------------------------
// Column-normalize a [3, W] direction matrix
// ---------------------------------------------------------------------------
__global__ void norm_cols_kernel(const float* __restrict__ D, float* __restrict__ Dn, int W) {
    int c = blockIdx.x * 256 + threadIdx.x;
    if (c >= W) return;
    float x = D[c], y = D[W + c], z = D[2 * W + c];
    float n = sqrtf(x * x + y * y + z * z);
    float r = 1.0f / fmaxf(n, 1e-12f);
    Dn[c] = x * r; Dn[W + c] = y * r; Dn[2 * W + c] = z * r;
}

// ---------------------------------------------------------------------------
// Brute-force kNN: per query, keep sorted top-11 (dist, idx) lexicographic.
// Drop rank 0 (self). Outputs idx10 (ranks 1..10) and optionally idx4 (1..4).
// N must be a multiple of 128. grid = (N/128, BATCH), block = 128
// ---------------------------------------------------------------------------
__global__ void knn_kernel(const float* __restrict__ v, int N,
                           int* __restrict__ idx10, int* __restrict__ idx4) {
    int b = blockIdx.y;
    int i = blockIdx.x * 128 + threadIdx.x;
    const float* vb = v + (long)b * N * 3;
    float px = vb[i * 3 + 0], py = vb[i * 3 + 1], pz = vb[i * 3 + 2];
    float pq = px * px + py * py + pz * pz;

    float d[11];
    int   ix[11];
#pragma unroll
    for (int k = 0; k < 11; k++) { d[k] = 1e30f; ix[k] = 0x7fffffff; }

    __shared__ float sx[128], sy[128], sz[128], sq[128];
    int t = threadIdx.x;
    for (int j0 = 0; j0 < N; j0 += 128) {
        __syncthreads();
        float cx = vb[(j0 + t) * 3 + 0];
        float cy = vb[(j0 + t) * 3 + 1];
        float cz = vb[(j0 + t) * 3 + 2];
        sx[t] = cx; sy[t] = cy; sz[t] = cz;
        sq[t] = cx * cx + cy * cy + cz * cz;
        __syncthreads();
        for (int jj = 0; jj < 128; jj++) {
            float dot = px * sx[jj] + py * sy[jj] + pz * sz[jj];
            float dist = pq + sq[jj] - 2.0f * dot;
            int j = j0 + jj;
            if (dist < d[10] || (dist == d[10] && j < ix[10])) {
                d[10] = dist; ix[10] = j;
#pragma unroll
                for (int k = 10; k > 0; --k) {
                    bool sw = (d[k] < d[k - 1]) || (d[k] == d[k - 1] && ix[k] < ix[k - 1]);
                    if (sw) {
                        float td = d[k]; d[k] = d[k - 1]; d[k - 1] = td;
                        int ti = ix[k]; ix[k] = ix[k - 1]; ix[k - 1] = ti;
                    }
                }
            }
        }
    }
    long base = ((long)b * N + i);
#pragma unroll
    for (int n = 0; n < 10; n++) idx10[base * 10 + n] = ix[n + 1];
    if (idx4) {
#pragma unroll
        for (int n = 0; n < 4; n++) idx4[base * 4 + n] = ix[n + 1];
    }
}

// ---------------------------------------------------------------------------
// Unit direction vectors toward the 10 neighbors
// ---------------------------------------------------------------------------
__global__ void dirs_kernel(const float* __restrict__ v, const int* __restrict__ idx10,
                            float* __restrict__ dirs, int N, int total) {
    int tt = blockIdx.x * 256 + threadIdx.x;
    if (tt >= total) return;
    int pt = tt / 10;          // b*N + i
    int b = pt / N;
    int i = pt - b * N;
    int j = idx10[tt];
    const float* vb = v + (long)b * N * 3;
    float dx = vb[j * 3 + 0] - vb[i * 3 + 0];
    float dy = vb[j * 3 + 1] - vb[i * 3 + 1];
    float dz = vb[j * 3 + 2] - vb[i * 3 + 2];
    float n = sqrtf(dx * dx + dy * dy + dz * dz);
    float r = 1.0f / fmaxf(n, 1e-12f);
    dirs[tt * 3 + 0] = dx * r;
    dirs[tt * 3 + 1] = dy * r;
    dirs[tt * 3 + 2] = dz * r;
}

// ---------------------------------------------------------------------------
// conv_surface: out[c] = silu( sum_s max_n silu(dir_n . d0col[s*128+c]) )
// grid = BATCH*NV blocks, 128 threads
// ---------------------------------------------------------------------------
__global__ void conv_surface_kernel(const float* __restrict__ dirs,
                                    const float* __restrict__ dn,
                                    float* __restrict__ fm0) {
    int pt = blockIdx.x;
    int c = threadIdx.x;
    __shared__ float sd[30];
    if (c < 30) sd[c] = dirs[(long)pt * 30 + c];
    __syncthreads();
    float acc = 0.0f;
#pragma unroll
    for (int s = 0; s < 7; s++) {
        int col = s * 128 + c;
        float dx = dn[col], dy = dn[896 + col], dz = dn[1792 + col];
        float m = -1e30f;
#pragma unroll
        for (int n = 0; n < 10; n++) {
            float t = sd[3 * n] * dx + sd[3 * n + 1] * dy + sd[3 * n + 2] * dz;
            m = fmaxf(m, silu_unit(t));
        }
        acc += m;
    }
    fm0[(long)pt * 128 + c] = silu_full(acc);
}

// ---------------------------------------------------------------------------
// SIMT fp32 GEMM with bias: C[M,N] = A[M,K] @ B[K,N] + bias
// 64x64 tile, BK=16, 256 threads, 4x4 micro-tile. M%64==0, N%64==0, K%16==0.
// ---------------------------------------------------------------------------
__global__ void gemm_bias_kernel(const float* __restrict__ A, const float* __restrict__ B,
                                 const float* __restrict__ bias, float* __restrict__ C,
                                 int M, int N, int K) {
    __shared__ float As[16][64];
    __shared__ float Bs[16][64];
    const int tid = threadIdx.x;
    const int tx = tid & 15;
    const int ty = tid >> 4;
    const int bm = blockIdx.y * 64;
    const int bn = blockIdx.x * 64;
    const int arow = tid >> 2;
    const int acol = (tid & 3) << 2;
    const int brow = tid >> 4;
    const int bcol = (tid & 15) << 2;
    float acc[4][4] = {};

    for (int k0 = 0; k0 < K; k0 += 16) {
        float4 av = *(const float4*)(A + (long)(bm + arow) * K + k0 + acol);
        float4 bv = *(const float4*)(B + (long)(k0 + brow) * N + bn + bcol);
        As[acol + 0][arow] = av.x;
        As[acol + 1][arow] = av.y;
        As[acol + 2][arow] = av.z;
        As[acol + 3][arow] = av.w;
        *(float4*)(&Bs[brow][bcol]) = bv;
        __syncthreads();
#pragma unroll
        for (int k = 0; k < 16; k++) {
            float4 a = *(const float4*)(&As[k][ty << 2]);
            float4 bq = *(const float4*)(&Bs[k][tx << 2]);
            acc[0][0] = fmaf(a.x, bq.x, acc[0][0]);
            acc[0][1] = fmaf(a.x, bq.y, acc[0][1]);
            acc[0][2] = fmaf(a.x, bq.z, acc[0][2]);
            acc[0][3] = fmaf(a.x, bq.w, acc[0][3]);
            acc[1][0] = fmaf(a.y, bq.x, acc[1][0]);
            acc[1][1] = fmaf(a.y, bq.y, acc[1][1]);
            acc[1][2] = fmaf(a.y, bq.z, acc[1][2]);
            acc[1][3] = fmaf(a.y, bq.w, acc[1][3]);
            acc[2][0] = fmaf(a.z, bq.x, acc[2][0]);
            acc[2][1] = fmaf(a.z, bq.y, acc[2][1]);
            acc[2][2] = fmaf(a.z, bq.z, acc[2][2]);
            acc[2][3] = fmaf(a.z, bq.w, acc[2][3]);
            acc[3][0] = fmaf(a.w, bq.x, acc[3][0]);
            acc[3][1] = fmaf(a.w, bq.y, acc[3][1]);
            acc[3][2] = fmaf(a.w, bq.z, acc[3][2]);
            acc[3][3] = fmaf(a.w, bq.w, acc[3][3]);
        }
        __syncthreads();
    }
    float4 bs = *(const float4*)(bias + bn + (tx << 2));
#pragma unroll
    for (int q = 0; q < 4; q++) {
        int row = bm + (ty << 2) + q;
        float4 o;
        o.x = acc[q][0] + bs.x;
        o.y = acc[q][1] + bs.y;
        o.z = acc[q][2] + bs.z;
        o.w = acc[q][3] + bs.w;
        *(float4*)(C + (long)row * N + bn + (tx << 2)) = o;
    }
}

// ---------------------------------------------------------------------------
// conv_layer: out[c] = feat[pt][c] + sum_s max_n silu(dir_n.col)*feat[nbr][C+s*C+c]
// grid = BATCH*Npts, block = C threads
// ---------------------------------------------------------------------------
template <int C>
__global__ void conv_layer_kernel(const float* __restrict__ feat,
                                  const float* __restrict__ dirs,
                                  const int* __restrict__ idx,
                                  const float* __restrict__ dirn,
                                  float* __restrict__ out, int Npts) {
    const int F = 8 * C;
    const int W = 7 * C;
    int pt = blockIdx.x;
    int b = pt / Npts;
    int c = threadIdx.x;
    __shared__ float sd[30];
    __shared__ int soff[10];
    if (c < 10) {
        int j = idx[(long)pt * 10 + c];
        soff[c] = (b * Npts + j) * F + C;
    }
    if (c < 30) sd[c] = dirs[(long)pt * 30 + c];
    __syncthreads();
    float center = feat[(long)pt * F + c];
    float acc = 0.0f;
    for (int s = 0; s < 7; s++) {
        int col = s * C + c;
        float dx = dirn[col], dy = dirn[W + col], dz = dirn[2 * W + col];
        float m = -1e30f;
#pragma unroll
        for (int n = 0; n < 10; n++) {
            float t = silu_unit(sd[3 * n] * dx + sd[3 * n + 1] * dy + sd[3 * n + 2] * dz);
            m = fmaxf(m, t * feat[soff[n] + col]);
        }
        acc += m;
    }
    out[(long)pt * C + c] = center + acc;
}

// ---------------------------------------------------------------------------
// BatchNorm stats per channel over R rows; grid = C blocks, 256 threads
// ---------------------------------------------------------------------------
__global__ void bn_stats_kernel(const float* __restrict__ X, int R, int C,
                                float* __restrict__ mean, float* __restrict__ rstd) {
    int c = blockIdx.x;
    float s = 0.0f, s2 = 0.0f;
    for (int r = threadIdx.x; r < R; r += 256) {
        float v = X[(long)r * C + c];
        s += v;
        s2 += v * v;
    }
    __shared__ float sh[256], sh2[256];
    sh[threadIdx.x] = s; sh2[threadIdx.x] = s2;
    __syncthreads();
    for (int st = 128; st > 0; st >>= 1) {
        if (threadIdx.x < st) {
            sh[threadIdx.x] += sh[threadIdx.x + st];
            sh2[threadIdx.x] += sh2[threadIdx.x + st];
        }
        __syncthreads();
    }
    if (threadIdx.x == 0) {
        float m = sh[0] / (float)R;
        float var = sh2[0] / (float)R - m * m;
        mean[c] = m;
        rstd[c] = rsqrtf(var + 1e-5f);
    }
}

__global__ void bn_apply_silu_kernel(const float* __restrict__ X,
                                     const float* __restrict__ mean, const float* __restrict__ rstd,
                                     const float* __restrict__ g, const float* __restrict__ bb,
                                     float* __restrict__ Y, int total, int C) {
    int i = blockIdx.x * 256 + threadIdx.x;
    if (i >= total) return;
    int c = i % C;
    float y = (X[i] - mean[c]) * rstd[c] * g[c] + bb[c];
    Y[i] = silu_full(y);
}

// ---------------------------------------------------------------------------
// Fused 4-NN max-pool + permutation gather (+ point coord gather)
// grid = BATCH*Pout, block = C threads
// ---------------------------------------------------------------------------
template <int C>
__global__ void pool_gather_kernel(const float* __restrict__ fm, const int* __restrict__ idx4,
                                   const int* __restrict__ perm, const float* __restrict__ vin,
                                   float* __restrict__ fout, float* __restrict__ vout,
                                   int Nin, int Pout) {
    int bp = blockIdx.x;
    int b = bp / Pout;
    int p = bp - b * Pout;
    int c = threadIdx.x;
    __shared__ int si;
    __shared__ int sj[4];
    if (c == 0) si = perm[p];
    __syncthreads();
    if (c < 4) sj[c] = idx4[((long)b * Nin + si) * 4 + c];
    __syncthreads();
    float m = -1e30f;
#pragma unroll
    for (int n = 0; n < 4; n++)
        m = fmaxf(m, fm[((long)b * Nin + sj[n]) * C + c]);
    fout[(long)bp * C + c] = m;
    if (c < 3) vout[(long)bp * 3 + c] = vin[((long)b * Nin + si) * 3 + c];
}

// ---------------------------------------------------------------------------
// Nearest source index for each target point (argmin, first-index ties)
// grid = (Nt/128, BATCH), block 128. Ns multiple of 128.
// ---------------------------------------------------------------------------
__global__ void nearest_kernel(const float* __restrict__ tgt, const float* __restrict__ src,
                               int Nt, int Ns, int* __restrict__ out) {
    int b = blockIdx.y;
    int i = blockIdx.x * 128 + threadIdx.x;
    const float* tb = tgt + (long)b * Nt * 3;
    const float* sb = src + (long)b * Ns * 3;
    float px = tb[i * 3 + 0], py = tb[i * 3 + 1], pz = tb[i * 3 + 2];
    float pq = px * px + py * py + pz * pz;
    float best = 1e30f;
    int bj = 0;
    __shared__ float sx[128], sy[128], sz[128], sq[128];
    int t = threadIdx.x;
    for (int j0 = 0; j0 < Ns; j0 += 128) {
        __syncthreads();
        float cx = sb[(j0 + t) * 3 + 0];
        float cy = sb[(j0 + t) * 3 + 1];
        float cz = sb[(j0 + t) * 3 + 2];
        sx[t] = cx; sy[t] = cy; sz[t] = cz;
        sq[t] = cx * cx + cy * cy + cz * cz;
        __syncthreads();
        for (int jj = 0; jj < 128; jj++) {
            float dot = px * sx[jj] + py * sy[jj] + pz * sz[jj];
            float dist = pq + sq[jj] - 2.0f * dot;
            if (dist < best) { best = dist; bj = j0 + jj; }
        }
    }
    out[(long)b * Nt + i] = bj;
}

// ---------------------------------------------------------------------------
// Final concat + upsample. grid = BATCH*NV, 256 threads
// ---------------------------------------------------------------------------
__global__ void assemble_kernel(const float* __restrict__ fm0, const float* __restrict__ fm1,
                                const float* __restrict__ fm2, const float* __restrict__ fm3,
                                const float* __restrict__ fm4,
                                const int* __restrict__ n1, const int* __restrict__ n2,
                                float* __restrict__ out) {
    int pt = blockIdx.x;
    int b = pt >> 12;
    int j1 = n1[pt];
    int j2 = n2[pt];
    float* o = out + (long)pt * 1280;
    for (int c = threadIdx.x; c < 1280; c += 256) {
        float v;
        if (c < 128)       v = fm0[(long)pt * 128 + c];
        else if (c < 256)  v = fm1[(long)pt * 128 + (c - 128)];
        else if (c < 512)  v = fm2[((long)b * NP1 + j1) * 256 + (c - 256)];
        else if (c < 768)  v = fm3[((long)b * NP1 + j1) * 256 + (c - 512)];
        else               v = fm4[((long)b * NP2 + j2) * 512 + (c - 768)];
        o[c] = v;
    }
}

// ---------------------------------------------------------------------------
// Host driver
// ---------------------------------------------------------------------------
extern "C" void kernel_launch(void* const* d_in, const int* in_sizes, int n_in,
                              void* d_out, int out_size) {
    const float* x    = (const float*)d_in[0];
    const float* d0   = (const float*)d_in[1];
    const float* w1   = (const float*)d_in[2];
    const float* b1   = (const float*)d_in[3];
    const float* dir1 = (const float*)d_in[4];
    const float* g1   = (const float*)d_in[5];
    const float* bb1  = (const float*)d_in[6];
    const float* w2   = (const float*)d_in[7];
    const float* b2   = (const float*)d_in[8];
    const float* dir2 = (const float*)d_in[9];
    const float* g2   = (const float*)d_in[10];
    const float* bb2  = (const float*)d_in[11];
    const float* w3   = (const float*)d_in[12];
    const float* b3   = (const float*)d_in[13];
    const float* dir3 = (const float*)d_in[14];
    const float* g3   = (const float*)d_in[15];
    const float* bb3  = (const float*)d_in[16];
    const float* w4   = (const float*)d_in[17];
    const float* b4   = (const float*)d_in[18];
    const float* dir4 = (const float*)d_in[19];
    const int* perm1  = (const int*)d_in[20];
    const int* perm2  = (const int*)d_in[21];
    float* out = (float*)d_out;

    float *d0n, *dir1n, *dir2n, *dir3n, *dir4n;
    int *idx10_0, *idx4_0, *idx10_1, *idx4_1, *idx10_2, *n1, *n2;
    float *dirs0, *dirs1, *dirs2;
    float *fm0, *feat1, *conv1, *fm1, *v1, *f1;
    float *feat2, *conv2, *fm2, *feat3, *conv3, *fm3;
    float *v2, *f2, *feat4, *fm4, *mean, *rstd;

    cudaGetSymbolAddress((void**)&d0n,  g_d0n);
    cudaGetSymbolAddress((void**)&dir1n, g_dir1n);
    cudaGetSymbolAddress((void**)&dir2n, g_dir2n);
    cudaGetSymbolAddress((void**)&dir3n, g_dir3n);
    cudaGetSymbolAddress((void**)&dir4n, g_dir4n);
    cudaGetSymbolAddress((void**)&idx10_0, g_idx10_0);
    cudaGetSymbolAddress((void**)&idx4_0,  g_idx4_0);
    cudaGetSymbolAddress((void**)&dirs0,   g_dirs0);
    cudaGetSymbolAddress((void**)&fm0,     g_fm0);
    cudaGetSymbolAddress((void**)&feat1,   g_feat1);
    cudaGetSymbolAddress((void**)&conv1,   g_conv1);
    cudaGetSymbolAddress((void**)&fm1,     g_fm1);
    cudaGetSymbolAddress((void**)&v1,      g_v1);
    cudaGetSymbolAddress((void**)&f1,      g_f1);
    cudaGetSymbolAddress((void**)&idx10_1, g_idx10_1);
    cudaGetSymbolAddress((void**)&idx4_1,  g_idx4_1);
    cudaGetSymbolAddress((void**)&dirs1,   g_dirs1);
    cudaGetSymbolAddress((void**)&feat2,   g_feat2);
    cudaGetSymbolAddress((void**)&conv2,   g_conv2);
    cudaGetSymbolAddress((void**)&fm2,     g_fm2);
    cudaGetSymbolAddress((void**)&feat3,   g_feat3);
    cudaGetSymbolAddress((void**)&conv3,   g_conv3);
    cudaGetSymbolAddress((void**)&fm3,     g_fm3);
    cudaGetSymbolAddress((void**)&v2,      g_v2);
    cudaGetSymbolAddress((void**)&f2,      g_f2);
    cudaGetSymbolAddress((void**)&idx10_2, g_idx10_2);
    cudaGetSymbolAddress((void**)&dirs2,   g_dirs2);
    cudaGetSymbolAddress((void**)&feat4,   g_feat4);
    cudaGetSymbolAddress((void**)&fm4,     g_fm4);
    cudaGetSymbolAddress((void**)&n1,      g_n1);
    cudaGetSymbolAddress((void**)&n2,      g_n2);
    cudaGetSymbolAddress((void**)&mean,    g_mean);
    cudaGetSymbolAddress((void**)&rstd,    g_rstd);

    // Normalize direction matrices
    norm_cols_kernel<<<(896 + 255) / 256, 256>>>(d0,   d0n,   896);
    norm_cols_kernel<<<(896 + 255) / 256, 256>>>(dir1, dir1n, 896);
    norm_cols_kernel<<<(1792 + 255) / 256, 256>>>(dir2, dir2n, 1792);
    norm_cols_kernel<<<(1792 + 255) / 256, 256>>>(dir3, dir3n, 1792);
    norm_cols_kernel<<<(3584 + 255) / 256, 256>>>(dir4, dir4n, 3584);

    // ---- Level 0 (V = 4096) ----
    knn_kernel<<<dim3(NV / 128, BATCH), 128>>>(x, NV, idx10_0, idx4_0);
    dirs_kernel<<<(BATCH * NV * 10 + 255) / 256, 256>>>(x, idx10_0, dirs0, NV, BATCH * NV * 10);
    conv_surface_kernel<<<BATCH * NV, 128>>>(dirs0, d0n, fm0);
    gemm_bias_kernel<<<dim3(1024 / 64, (BATCH * NV) / 64), 256>>>(fm0, w1, b1, feat1, BATCH * NV, 1024, 128);
    conv_layer_kernel<128><<<BATCH * NV, 128>>>(feat1, dirs0, idx10_0, dir1n, conv1, NV);
    bn_stats_kernel<<<128, 256>>>(conv1, BATCH * NV, 128, mean, rstd);
    bn_apply_silu_kernel<<<(BATCH * NV * 128 + 255) / 256, 256>>>(conv1, mean, rstd, g1, bb1, fm1, BATCH * NV * 128, 128);
    pool_gather_kernel<128><<<BATCH * NP1, 128>>>(fm1, idx4_0, perm1, x, f1, v1, NV, NP1);

    // ---- Level 1 (V = 1024) ----
    knn_kernel<<<dim3(NP1 / 128, BATCH), 128>>>(v1, NP1, idx10_1, idx4_1);
    dirs_kernel<<<(BATCH * NP1 * 10 + 255) / 256, 256>>>(v1, idx10_1, dirs1, NP1, BATCH * NP1 * 10);
    gemm_bias_kernel<<<dim3(2048 / 64, (BATCH * NP1) / 64), 256>>>(f1, w2, b2, feat2, BATCH * NP1, 2048, 128);
    conv_layer_kernel<256><<<BATCH * NP1, 256>>>(feat2, dirs1, idx10_1, dir2n, conv2, NP1);
    bn_stats_kernel<<<256, 256>>>(conv2, BATCH * NP1, 256, mean, rstd);
    bn_apply_silu_kernel<<<(BATCH * NP1 * 256 + 255) / 256, 256>>>(conv2, mean, rstd, g2, bb2, fm2, BATCH * NP1 * 256, 256);
    gemm_bias_kernel<<<dim3(2048 / 64, (BATCH * NP1) / 64), 256>>>(fm2, w3, b3, feat3, BATCH * NP1, 2048, 256);
    conv_layer_kernel<256><<<BATCH * NP1, 256>>>(feat3, dirs1, idx10_1, dir3n, conv3, NP1);
    bn_stats_kernel<<<256, 256>>>(conv3, BATCH * NP1, 256, mean, rstd);
    bn_apply_silu_kernel<<<(BATCH * NP1 * 256 + 255) / 256, 256>>>(conv3, mean, rstd, g3, bb3, fm3, BATCH * NP1 * 256, 256);
    pool_gather_kernel<256><<<BATCH * NP2, 256>>>(fm3, idx4_1, perm2, v1, f2, v2, NP1, NP2);

    // ---- Level 2 (V = 256) ----
    knn_kernel<<<dim3(NP2 / 128, BATCH), 128>>>(v2, NP2, idx10_2, (int*)0);
    dirs_kernel<<<(BATCH * NP2 * 10 + 255) / 256, 256>>>(v2, idx10_2, dirs2, NP2, BATCH * NP2 * 10);
    gemm_bias_kernel<<<dim3(4096 / 64, (BATCH * NP2) / 64), 256>>>(f2, w4, b4, feat4, BATCH * NP2, 4096, 256);
    conv_layer_kernel<512><<<BATCH * NP2, 512>>>(feat4, dirs2, idx10_2, dir4n, fm4, NP2);

    // ---- Upsample + concat ----
    nearest_kernel<<<dim3(NV / 128, BATCH), 128>>>(x, v1, NV, NP1, n1);
    nearest_kernel<<<dim3(NV / 128, BATCH), 128>>>(x, v2, NV, NP2, n2);
    assemble_kernel<<<BATCH * NV, 256>>>(fm0, fm1, fm2, fm3, fm4, n1, n2, out);
}

// round 2
// speedup vs baseline: 1.0434x; 1.0434x over previous
#include <cuda_runtime.h>
#include <math.h>

#define BATCH 2
#define NV    4096
#define NP1   1024
#define NP2   256

// ---------------------------------------------------------------------------
// Device scratch (allocation-free rule: __device__ globals)
// ---------------------------------------------------------------------------
__device__ float g_d0n  [3*896];
__device__ float g_dir1n[3*896];
__device__ float g_dir2n[3*1792];
__device__ float g_dir3n[3*1792];
__device__ float g_dir4n[3*3584];

__device__ int   g_idx10_0[BATCH*NV*10];
__device__ int   g_idx4_0 [BATCH*NV*4];
__device__ float g_dirs0  [BATCH*NV*10*3];
__device__ float g_fm0    [BATCH*NV*128];
__device__ float g_feat1  [BATCH*NV*1024];
__device__ float g_conv1  [BATCH*NV*128];
__device__ float g_fm1    [BATCH*NV*128];

__device__ float g_v1 [BATCH*NP1*3];
__device__ float g_f1 [BATCH*NP1*128];
__device__ int   g_idx10_1[BATCH*NP1*10];
__device__ int   g_idx4_1 [BATCH*NP1*4];
__device__ float g_dirs1  [BATCH*NP1*10*3];
__device__ float g_feat2  [BATCH*NP1*2048];
__device__ float g_conv2  [BATCH*NP1*256];
__device__ float g_fm2    [BATCH*NP1*256];
__device__ float g_feat3  [BATCH*NP1*2048];
__device__ float g_conv3  [BATCH*NP1*256];
__device__ float g_fm3    [BATCH*NP1*256];

__device__ float g_v2 [BATCH*NP2*3];
__device__ float g_f2 [BATCH*NP2*256];
__device__ int   g_idx10_2[BATCH*NP2*10];
__device__ float g_dirs2  [BATCH*NP2*10*3];
__device__ float g_feat4  [BATCH*NP2*4096];
__device__ float g_fm4    [BATCH*NP2*512];

__device__ int   g_n1[BATCH*NV];
__device__ int   g_n2[BATCH*NV];
__device__ float g_mean[512];
__device__ float g_rstd[512];

// ---------------------------------------------------------------------------
// Math helpers
// ---------------------------------------------------------------------------
// SiLU for arguments guaranteed in [-1,1] (dot of two unit vectors).
// abs error <= ~2e-6 on [-1,1]. Runs on the FMA pipe (no MUFU).
__device__ __forceinline__ float silu_unit(float y) {
    float u = y * y;
    float p = fmaf(u, 2.1357672e-5f, -2.1081349e-4f);
    p = fmaf(u, p, 2.0833333e-3f);
    p = fmaf(u, p, -2.0833333e-2f);
    p = fmaf(u, p, 0.25f);
    float s = fmaf(y, p, 0.5f);
    return y * s;
}

__device__ __forceinline__ float silu_full(float y) {
    return y / (1.0f + __expf(-y));
}

// ---------------------------------------------------------------------------
// Column-normalize a [3, W] direction matrix
// ---------------------------------------------------------------------------
__global__ void norm_cols_kernel(const float* __restrict__ D, float* __restrict__ Dn, int W) {
    int c = blockIdx.x * 256 + threadIdx.x;
    if (c >= W) return;
    float x = D[c], y = D[W + c], z = D[2 * W + c];
    float n = sqrtf(x * x + y * y + z * z);
    float r = 1.0f / fmaxf(n, 1e-12f);
    Dn[c] = x * r; Dn[W + c] = y * r; Dn[2 * W + c] = z * r;
}

// ---------------------------------------------------------------------------
// Brute-force kNN + fused unit-direction output.
// Per query keeps sorted top-11 (dist, idx) lexicographic; drops rank 0 (self).
// grid = (N/128, BATCH), block = 128
// ---------------------------------------------------------------------------
__global__ void knn_kernel(const float* __restrict__ v, int N,
                           int* __restrict__ idx10, int* __restrict__ idx4,
                           float* __restrict__ dirs) {
    int b = blockIdx.y;
    int i = blockIdx.x * 128 + threadIdx.x;
    const float* vb = v + (long)b * N * 3;
    float px = vb[i * 3 + 0], py = vb[i * 3 + 1], pz = vb[i * 3 + 2];
    float pq = px * px + py * py + pz * pz;

    float d[11];
    int   ix[11];
#pragma unroll
    for (int k = 0; k < 11; k++) { d[k] = 1e30f; ix[k] = 0x7fffffff; }

    __shared__ float sx[128], sy[128], sz[128], sq[128];
    int t = threadIdx.x;
    for (int j0 = 0; j0 < N; j0 += 128) {
        __syncthreads();
        float cx = vb[(j0 + t) * 3 + 0];
        float cy = vb[(j0 + t) * 3 + 1];
        float cz = vb[(j0 + t) * 3 + 2];
        sx[t] = cx; sy[t] = cy; sz[t] = cz;
        sq[t] = cx * cx + cy * cy + cz * cz;
        __syncthreads();
        for (int jj = 0; jj < 128; jj++) {
            float dot = px * sx[jj] + py * sy[jj] + pz * sz[jj];
            float dist = pq + sq[jj] - 2.0f * dot;
            int j = j0 + jj;
            if (dist < d[10] || (dist == d[10] && j < ix[10])) {
                d[10] = dist; ix[10] = j;
#pragma unroll
                for (int k = 10; k > 0; --k) {
                    bool sw = (d[k] < d[k - 1]) || (d[k] == d[k - 1] && ix[k] < ix[k - 1]);
                    if (sw) {
                        float td = d[k]; d[k] = d[k - 1]; d[k - 1] = td;
                        int ti = ix[k]; ix[k] = ix[k - 1]; ix[k - 1] = ti;
                    }
                }
            }
        }
    }
    long base = ((long)b * N + i);
#pragma unroll
    for (int n = 0; n < 10; n++) idx10[base * 10 + n] = ix[n + 1];
    if (idx4) {
#pragma unroll
        for (int n = 0; n < 4; n++) idx4[base * 4 + n] = ix[n + 1];
    }
    // fused unit directions
#pragma unroll
    for (int n = 0; n < 10; n++) {
        int j = ix[n + 1];
        float dx = vb[j * 3 + 0] - px;
        float dy = vb[j * 3 + 1] - py;
        float dz = vb[j * 3 + 2] - pz;
        float nn = sqrtf(dx * dx + dy * dy + dz * dz);
        float r = 1.0f / fmaxf(nn, 1e-12f);
        dirs[base * 30 + n * 3 + 0] = dx * r;
        dirs[base * 30 + n * 3 + 1] = dy * r;
        dirs[base * 30 + n * 3 + 2] = dz * r;
    }
}

// ---------------------------------------------------------------------------
// conv_surface: out[c] = silu( sum_s max_n silu(dir_n . d0col[s*128+c]) )
// grid = BATCH*NV blocks, 128 threads
// ---------------------------------------------------------------------------
__global__ void conv_surface_kernel(const float* __restrict__ dirs,
                                    const float* __restrict__ dn,
                                    float* __restrict__ fm0) {
    int pt = blockIdx.x;
    int c = threadIdx.x;
    __shared__ float sd[30];
    if (c < 30) sd[c] = dirs[(long)pt * 30 + c];
    __syncthreads();
    float rx[10], ry[10], rz[10];
#pragma unroll
    for (int n = 0; n < 10; n++) { rx[n] = sd[3*n]; ry[n] = sd[3*n+1]; rz[n] = sd[3*n+2]; }
    float acc = 0.0f;
#pragma unroll
    for (int s = 0; s < 7; s++) {
        int col = s * 128 + c;
        float dx = dn[col], dy = dn[896 + col], dz = dn[1792 + col];
        float m = -1e30f;
#pragma unroll
        for (int n = 0; n < 10; n++) {
            float tt = rx[n] * dx + ry[n] * dy + rz[n] * dz;
            m = fmaxf(m, silu_unit(tt));
        }
        acc += m;
    }
    fm0[(long)pt * 128 + c] = silu_full(acc);
}

// ---------------------------------------------------------------------------
// SIMT fp32 GEMM with bias: C[M,N] = A[M,K] @ B[K,N] + bias
// 128x128 tile, BK=8, 256 threads, 8x8 micro-tile, double-buffered smem.
// Requires M%128==0, N%128==0, K%8==0.
// ---------------------------------------------------------------------------
__global__ __launch_bounds__(256, 2)
void gemm_bias_kernel(const float* __restrict__ A, const float* __restrict__ B,
                      const float* __restrict__ bias, float* __restrict__ C,
                      int M, int N, int K) {
    __shared__ float As[2][8][128];
    __shared__ float Bs[2][8][128];
    const int tid = threadIdx.x;
    const int bm = blockIdx.y * 128;
    const int bn = blockIdx.x * 128;

    // global load mapping
    const int arow = tid >> 1;           // 0..127
    const int akk  = (tid & 1) << 2;     // 0 or 4
    const int brow = tid >> 5;           // 0..7
    const int bcol = (tid & 31) << 2;    // 0..124

    const float4* Ap = (const float4*)(A + (long)(bm + arow) * K + akk);
    const float4* Bp = (const float4*)(B + (long)brow * N + bn + bcol);
    const long astep = 2;                 // 8 floats along K
    const long bstep = 2 * (long)N / 4 * 4 / 4; // 8*N floats = 2N float4
    // (computed explicitly below to avoid confusion)

    const int r0 = (tid >> 4) << 3;      // 0..120
    const int c0 = (tid & 15) << 3;      // 0..120

    float acc[8][8];
#pragma unroll
    for (int i = 0; i < 8; i++)
#pragma unroll
        for (int j = 0; j < 8; j++) acc[i][j] = 0.0f;

    const int T = K >> 3;

    // prologue: stage 0
    float4 av = Ap[0];
    float4 bv = Bp[0];
    As[0][akk + 0][arow] = av.x;
    As[0][akk + 1][arow] = av.y;
    As[0][akk + 2][arow] = av.z;
    As[0][akk + 3][arow] = av.w;
    *(float4*)&Bs[0][brow][bcol] = bv;
    __syncthreads();

    for (int t = 0; t < T; t++) {
        const int cur = t & 1;
        if (t + 1 < T) {
            av = Ap[(long)(t + 1) * astep];
            bv = *(const float4*)((const float*)Bp + (long)(t + 1) * 8 * N);
        }
#pragma unroll
        for (int k = 0; k < 8; k++) {
            float4 a0 = *(const float4*)&As[cur][k][r0];
            float4 a1 = *(const float4*)&As[cur][k][r0 + 4];
            float4 b0 = *(const float4*)&Bs[cur][k][c0];
            float4 b1 = *(const float4*)&Bs[cur][k][c0 + 4];
            float ar[8] = {a0.x, a0.y, a0.z, a0.w, a1.x, a1.y, a1.z, a1.w};
            float br[8] = {b0.x, b0.y, b0.z, b0.w, b1.x, b1.y, b1.z, b1.w};
#pragma unroll
            for (int i = 0; i < 8; i++)
#pragma unroll
                for (int j = 0; j < 8; j++)
                    acc[i][j] = fmaf(ar[i], br[j], acc[i][j]);
        }
        if (t + 1 < T) {
            const int nxt = cur ^ 1;
            As[nxt][akk + 0][arow] = av.x;
            As[nxt][akk + 1][arow] = av.y;
            As[nxt][akk + 2][arow] = av.z;
            As[nxt][akk + 3][arow] = av.w;
            *(float4*)&Bs[nxt][brow][bcol] = bv;
            __syncthreads();
        }
    }

    float4 bs0 = *(const float4*)(bias + bn + c0);
    float4 bs1 = *(const float4*)(bias + bn + c0 + 4);
    float bb[8] = {bs0.x, bs0.y, bs0.z, bs0.w, bs1.x, bs1.y, bs1.z, bs1.w};
#pragma unroll
    for (int i = 0; i < 8; i++) {
        int row = bm + r0 + i;
        float4 o0, o1;
        o0.x = acc[i][0] + bb[0]; o0.y = acc[i][1] + bb[1];
        o0.z = acc[i][2] + bb[2]; o0.w = acc[i][3] + bb[3];
        o1.x = acc[i][4] + bb[4]; o1.y = acc[i][5] + bb[5];
        o1.z = acc[i][6] + bb[6]; o1.w = acc[i][7] + bb[7];
        *(float4*)(C + (long)row * N + bn + c0)     = o0;
        *(float4*)(C + (long)row * N + bn + c0 + 4) = o1;
    }
}

// ---------------------------------------------------------------------------
// conv_layer: out[c] = feat[pt][c] + sum_s max_n silu(dir_n.col)*feat[nbr][C+s*C+c]
// grid = BATCH*Npts, block = C threads
// ---------------------------------------------------------------------------
template <int C>
__global__ void conv_layer_kernel(const float* __restrict__ feat,
                                  const float* __restrict__ dirs,
                                  const int* __restrict__ idx,
                                  const float* __restrict__ dirn,
                                  float* __restrict__ out, int Npts) {
    const int F = 8 * C;
    const int W = 7 * C;
    int pt = blockIdx.x;
    int b = pt / Npts;
    int c = threadIdx.x;
    __shared__ float sd[30];
    __shared__ int soff[10];
    if (c < 10) {
        int j = idx[(long)pt * 10 + c];
        soff[c] = (b * Npts + j) * F + C;
    }
    if (c < 30) sd[c] = dirs[(long)pt * 30 + c];
    __syncthreads();
    float rx[10], ry[10], rz[10];
    int off[10];
#pragma unroll
    for (int n = 0; n < 10; n++) {
        rx[n] = sd[3*n]; ry[n] = sd[3*n+1]; rz[n] = sd[3*n+2];
        off[n] = soff[n];
    }
    float center = feat[(long)pt * F + c];
    float acc = 0.0f;
#pragma unroll
    for (int s = 0; s < 7; s++) {
        int col = s * C + c;
        float dx = dirn[col], dy = dirn[W + col], dz = dirn[2 * W + col];
        float m = -1e30f;
#pragma unroll
        for (int n = 0; n < 10; n++) {
            float tt = silu_unit(rx[n] * dx + ry[n] * dy + rz[n] * dz);
            m = fmaxf(m, tt * feat[off[n] + col]);
        }
        acc += m;
    }
    out[(long)pt * C + c] = center + acc;
}

// ---------------------------------------------------------------------------
// BatchNorm stats per channel over R rows; grid = C blocks, 256 threads
// ---------------------------------------------------------------------------
__global__ void bn_stats_kernel(const float* __restrict__ X, int R, int C,
                                float* __restrict__ mean, float* __restrict__ rstd) {
    int c = blockIdx.x;
    float s = 0.0f, s2 = 0.0f;
    for (int r = threadIdx.x; r < R; r += 256) {
        float v = X[(long)r * C + c];
        s += v;
        s2 += v * v;
    }
    __shared__ float sh[256], sh2[256];
    sh[threadIdx.x] = s; sh2[threadIdx.x] = s2;
    __syncthreads();
    for (int st = 128; st > 0; st >>= 1) {
        if (threadIdx.x < st) {
            sh[threadIdx.x] += sh[threadIdx.x + st];
            sh2[threadIdx.x] += sh2[threadIdx.x + st];
        }
        __syncthreads();
    }
    if (threadIdx.x == 0) {
        float m = sh[0] / (float)R;
        float var = sh2[0] / (float)R - m * m;
        mean[c] = m;
        rstd[c] = rsqrtf(var + 1e-5f);
    }
}

__global__ void bn_apply_silu_kernel(const float* __restrict__ X,
                                     const float* __restrict__ mean, const float* __restrict__ rstd,
                                     const float* __restrict__ g, const float* __restrict__ bb,
                                     float* __restrict__ Y, int total, int C) {
    int i = blockIdx.x * 256 + threadIdx.x;
    if (i >= total) return;
    int c = i % C;
    float y = (X[i] - mean[c]) * rstd[c] * g[c] + bb[c];
    Y[i] = silu_full(y);
}

// ---------------------------------------------------------------------------
// Fused 4-NN max-pool + permutation gather (+ point coord gather)
// grid = BATCH*Pout, block = C threads
// ---------------------------------------------------------------------------
template <int C>
__global__ void pool_gather_kernel(const float* __restrict__ fm, const int* __restrict__ idx4,
                                   const int* __restrict__ perm, const float* __restrict__ vin,
                                   float* __restrict__ fout, float* __restrict__ vout,
                                   int Nin, int Pout) {
    int bp = blockIdx.x;
    int b = bp / Pout;
    int p = bp - b * Pout;
    int c = threadIdx.x;
    __shared__ int si;
    __shared__ int sj[4];
    if (c == 0) si = perm[p];
    __syncthreads();
    if (c < 4) sj[c] = idx4[((long)b * Nin + si) * 4 + c];
    __syncthreads();
    float m = -1e30f;
#pragma unroll
    for (int n = 0; n < 4; n++)
        m = fmaxf(m, fm[((long)b * Nin + sj[n]) * C + c]);
    fout[(long)bp * C + c] = m;
    if (c < 3) vout[(long)bp * 3 + c] = vin[((long)b * Nin + si) * 3 + c];
}

// ---------------------------------------------------------------------------
// Nearest source index for each target point (argmin, first-index ties)
// ---------------------------------------------------------------------------
__global__ void nearest_kernel(const float* __restrict__ tgt, const float* __restrict__ src,
                               int Nt, int Ns, int* __restrict__ out) {
    int b = blockIdx.y;
    int i = blockIdx.x * 128 + threadIdx.x;
    const float* tb = tgt + (long)b * Nt * 3;
    const float* sb = src + (long)b * Ns * 3;
    float px = tb[i * 3 + 0], py = tb[i * 3 + 1], pz = tb[i * 3 + 2];
    float pq = px * px + py * py + pz * pz;
    float best = 1e30f;
    int bj = 0;
    __shared__ float sx[128], sy[128], sz[128], sq[128];
    int t = threadIdx.x;
    for (int j0 = 0; j0 < Ns; j0 += 128) {
        __syncthreads();
        float cx = sb[(j0 + t) * 3 + 0];
        float cy = sb[(j0 + t) * 3 + 1];
        float cz = sb[(j0 + t) * 3 + 2];
        sx[t] = cx; sy[t] = cy; sz[t] = cz;
        sq[t] = cx * cx + cy * cy + cz * cz;
        __syncthreads();
        for (int jj = 0; jj < 128; jj++) {
            float dot = px * sx[jj] + py * sy[jj] + pz * sz[jj];
            float dist = pq + sq[jj] - 2.0f * dot;
            if (dist < best) { best = dist; bj = j0 + jj; }
        }
    }
    out[(long)b * Nt + i] = bj;
}

// ---------------------------------------------------------------------------
// Final concat + upsample. grid = BATCH*NV, 256 threads
// ---------------------------------------------------------------------------
__global__ void assemble_kernel(const float* __restrict__ fm0, const float* __restrict__ fm1,
                                const float* __restrict__ fm2, const float* __restrict__ fm3,
                                const float* __restrict__ fm4,
                                const int* __restrict__ n1, const int* __restrict__ n2,
                                float* __restrict__ out) {
    int pt = blockIdx.x;
    int b = pt >> 12;
    int j1 = n1[pt];
    int j2 = n2[pt];
    float* o = out + (long)pt * 1280;
    for (int c = threadIdx.x; c < 1280; c += 256) {
        float v;
        if (c < 128)       v = fm0[(long)pt * 128 + c];
        else if (c < 256)  v = fm1[(long)pt * 128 + (c - 128)];
        else if (c < 512)  v = fm2[((long)b * NP1 + j1) * 256 + (c - 256)];
        else if (c < 768)  v = fm3[((long)b * NP1 + j1) * 256 + (c - 512)];
        else               v = fm4[((long)b * NP2 + j2) * 512 + (c - 768)];
        o[c] = v;
    }
}

// ---------------------------------------------------------------------------
// Host driver
// ---------------------------------------------------------------------------
extern "C" void kernel_launch(void* const* d_in, const int* in_sizes, int n_in,
                              void* d_out, int out_size) {
    const float* x    = (const float*)d_in[0];
    const float* d0   = (const float*)d_in[1];
    const float* w1   = (const float*)d_in[2];
    const float* b1   = (const float*)d_in[3];
    const float* dir1 = (const float*)d_in[4];
    const float* g1   = (const float*)d_in[5];
    const float* bb1  = (const float*)d_in[6];
    const float* w2   = (const float*)d_in[7];
    const float* b2   = (const float*)d_in[8];
    const float* dir2 = (const float*)d_in[9];
    const float* g2   = (const float*)d_in[10];
    const float* bb2  = (const float*)d_in[11];
    const float* w3   = (const float*)d_in[12];
    const float* b3   = (const float*)d_in[13];
    const float* dir3 = (const float*)d_in[14];
    const float* g3   = (const float*)d_in[15];
    const float* bb3  = (const float*)d_in[16];
    const float* w4   = (const float*)d_in[17];
    const float* b4   = (const float*)d_in[18];
    const float* dir4 = (const float*)d_in[19];
    const int* perm1  = (const int*)d_in[20];
    const int* perm2  = (const int*)d_in[21];
    float* out = (float*)d_out;

    float *d0n, *dir1n, *dir2n, *dir3n, *dir4n;
    int *idx10_0, *idx4_0, *idx10_1, *idx4_1, *idx10_2, *n1, *n2;
    float *dirs0, *dirs1, *dirs2;
    float *fm0, *feat1, *conv1, *fm1, *v1, *f1;
    float *feat2, *conv2, *fm2, *feat3, *conv3, *fm3;
    float *v2, *f2, *feat4, *fm4, *mean, *rstd;

    cudaGetSymbolAddress((void**)&d0n,  g_d0n);
    cudaGetSymbolAddress((void**)&dir1n, g_dir1n);
    cudaGetSymbolAddress((void**)&dir2n, g_dir2n);
    cudaGetSymbolAddress((void**)&dir3n, g_dir3n);
    cudaGetSymbolAddress((void**)&dir4n, g_dir4n);
    cudaGetSymbolAddress((void**)&idx10_0, g_idx10_0);
    cudaGetSymbolAddress((void**)&idx4_0,  g_idx4_0);
    cudaGetSymbolAddress((void**)&dirs0,   g_dirs0);
    cudaGetSymbolAddress((void**)&fm0,     g_fm0);
    cudaGetSymbolAddress((void**)&feat1,   g_feat1);
    cudaGetSymbolAddress((void**)&conv1,   g_conv1);
    cudaGetSymbolAddress((void**)&fm1,     g_fm1);
    cudaGetSymbolAddress((void**)&v1,      g_v1);
    cudaGetSymbolAddress((void**)&f1,      g_f1);
    cudaGetSymbolAddress((void**)&idx10_1, g_idx10_1);
    cudaGetSymbolAddress((void**)&idx4_1,  g_idx4_1);
    cudaGetSymbolAddress((void**)&dirs1,   g_dirs1);
    cudaGetSymbolAddress((void**)&feat2,   g_feat2);
    cudaGetSymbolAddress((void**)&conv2,   g_conv2);
    cudaGetSymbolAddress((void**)&fm2,     g_fm2);
    cudaGetSymbolAddress((void**)&feat3,   g_feat3);
    cudaGetSymbolAddress((void**)&conv3,   g_conv3);
    cudaGetSymbolAddress((void**)&fm3,     g_fm3);
    cudaGetSymbolAddress((void**)&v2,      g_v2);
    cudaGetSymbolAddress((void**)&f2,      g_f2);
    cudaGetSymbolAddress((void**)&idx10_2, g_idx10_2);
    cudaGetSymbolAddress((void**)&dirs2,   g_dirs2);
    cudaGetSymbolAddress((void**)&feat4,   g_feat4);
    cudaGetSymbolAddress((void**)&fm4,     g_fm4);
    cudaGetSymbolAddress((void**)&n1,      g_n1);
    cudaGetSymbolAddress((void**)&n2,      g_n2);
    cudaGetSymbolAddress((void**)&mean,    g_mean);
    cudaGetSymbolAddress((void**)&rstd,    g_rstd);

    // Launch order arranged so ncu (-s 5 -c 1) captures gemm_bias_kernel (launch #6).
    norm_cols_kernel<<<4, 256>>>(d0, d0n, 896);                                     // 0
    knn_kernel<<<dim3(NV / 128, BATCH), 128>>>(x, NV, idx10_0, idx4_0, dirs0);      // 1
    conv_surface_kernel<<<BATCH * NV, 128>>>(dirs0, d0n, fm0);                      // 2
    norm_cols_kernel<<<4, 256>>>(dir1, dir1n, 896);                                 // 3
    norm_cols_kernel<<<7, 256>>>(dir2, dir2n, 1792);                                // 4
    gemm_bias_kernel<<<dim3(1024 / 128, (BATCH * NV) / 128), 256>>>(fm0, w1, b1, feat1, BATCH * NV, 1024, 128); // 5 <-- profiled
    norm_cols_kernel<<<7, 256>>>(dir3, dir3n, 1792);
    norm_cols_kernel<<<14, 256>>>(dir4, dir4n, 3584);

    conv_layer_kernel<128><<<BATCH * NV, 128>>>(feat1, dirs0, idx10_0, dir1n, conv1, NV);
    bn_stats_kernel<<<128, 256>>>(conv1, BATCH * NV, 128, mean, rstd);
    bn_apply_silu_kernel<<<(BATCH * NV * 128 + 255) / 256, 256>>>(conv1, mean, rstd, g1, bb1, fm1, BATCH * NV * 128, 128);
    pool_gather_kernel<128><<<BATCH * NP1, 128>>>(fm1, idx4_0, perm1, x, f1, v1, NV, NP1);

    // ---- Level 1 (V = 1024) ----
    knn_kernel<<<dim3(NP1 / 128, BATCH), 128>>>(v1, NP1, idx10_1, idx4_1, dirs1);
    gemm_bias_kernel<<<dim3(2048 / 128, (BATCH * NP1) / 128), 256>>>(f1, w2, b2, feat2, BATCH * NP1, 2048, 128);
    conv_layer_kernel<256><<<BATCH * NP1, 256>>>(feat2, dirs1, idx10_1, dir2n, conv2, NP1);
    bn_stats_kernel<<<256, 256>>>(conv2, BATCH * NP1, 256, mean, rstd);
    bn_apply_silu_kernel<<<(BATCH * NP1 * 256 + 255) / 256, 256>>>(conv2, mean, rstd, g2, bb2, fm2, BATCH * NP1 * 256, 256);
    gemm_bias_kernel<<<dim3(2048 / 128, (BATCH * NP1) / 128), 256>>>(fm2, w3, b3, feat3, BATCH * NP1, 2048, 256);
    conv_layer_kernel<256><<<BATCH * NP1, 256>>>(feat3, dirs1, idx10_1, dir3n, conv3, NP1);
    bn_stats_kernel<<<256, 256>>>(conv3, BATCH * NP1, 256, mean, rstd);
    bn_apply_silu_kernel<<<(BATCH * NP1 * 256 + 255) / 256, 256>>>(conv3, mean, rstd, g3, bb3, fm3, BATCH * NP1 * 256, 256);
    pool_gather_kernel<256><<<BATCH * NP2, 256>>>(fm3, idx4_1, perm2, v1, f2, v2, NP1, NP2);

    // ---- Level 2 (V = 256) ----
    knn_kernel<<<dim3(NP2 / 128, BATCH), 128>>>(v2, NP2, idx10_2, (int*)0, dirs2);
    gemm_bias_kernel<<<dim3(4096 / 128, (BATCH * NP2) / 128), 256>>>(f2, w4, b4, feat4, BATCH * NP2, 4096, 256);
    conv_layer_kernel<512><<<BATCH * NP2, 512>>>(feat4, dirs2, idx10_2, dir4n, fm4, NP2);

    // ---- Upsample + concat ----
    nearest_kernel<<<dim3(NV / 128, BATCH), 128>>>(x, v1, NV, NP1, n1);
    nearest_kernel<<<dim3(NV / 128, BATCH), 128>>>(x, v2, NV, NP2, n2);
    assemble_kernel<<<BATCH * NV, 256>>>(fm0, fm1, fm2, fm3, fm4, n1, n2, out);
}